// round 6
// baseline (speedup 1.0000x reference)
#include <cuda_runtime.h>
#include <cuda_bf16.h>

#define NB 2
#define NN 2048
#define NF 256
#define NH 8
#define NO 32

typedef unsigned long long ull;

// ---------------- f32x2 packed-math helpers (sm_103a FFMA2 path) --------------
__device__ __forceinline__ void ffma2(ull& d, ull a, ull b) {
    asm("fma.rn.f32x2 %0, %1, %2, %0;" : "+l"(d) : "l"(a), "l"(b));
}
__device__ __forceinline__ void fadd2(ull& d, ull a) {
    asm("add.rn.f32x2 %0, %1, %0;" : "+l"(d) : "l"(a));
}
__device__ __forceinline__ ull pack2(float x, float y) {
    ull r;
    asm("mov.b64 %0, {%1, %2};" : "=l"(r) : "f"(x), "f"(y));
    return r;
}
__device__ __forceinline__ float2 unpack2(ull v) {
    float2 r;
    asm("mov.b64 {%0, %1}, %2;" : "=f"(r.x), "=f"(r.y) : "l"(v));
    return r;
}

// ---------------- scratch (device globals; no allocation allowed) -------------
__device__ __align__(128) float    g_h [NB*NN*NF];   // layer input / stage-B output
__device__ __align__(128) float    g_hA[NB*NN*NF];   // stage-A attention output
__device__ __align__(128) float    g_Wh[NB*NN*NF];   // projected features (V)
__device__ __align__(128) float    g_Wc[NF*NF];      // packed per-layer head weights
__device__ __align__(128) float    g_s1[NB*NH*NN];
__device__ __align__(128) float    g_s2[NB*NH*NN];
__device__             float       g_M2[NB*NH];
__device__ __align__(128) unsigned g_bm[NB*NN*(NN/32)];  // adjacency bitmask

// ---------------- adjacency -> bitmask (runs once) ----------------------------
__global__ void bm_kernel(const int* __restrict__ adj) {
    int wid  = blockIdx.x * 8 + (threadIdx.x >> 5);
    int lane = threadIdx.x & 31;
    int word = wid & 63;
    int row  = wid >> 6;                       // b*NN + i
    int j = word * 32 + lane;
    int a = adj[(size_t)row * NN + j];
    unsigned bits = __ballot_sync(0xffffffffu, a != 0);
    if (lane == 0) g_bm[wid] = bits;
}

// ---------------- pack W_heads[l] into [F, H*O] column-major-by-head ----------
__global__ void pack_kernel(const float* __restrict__ Wheads, int l) {
    int f = blockIdx.x, c = threadIdx.x;
    g_Wc[f * NF + c] =
        Wheads[(((size_t)l * NH + (c >> 5)) * NF + f) * NO + (c & 31)];
}

// ---------------- GEMM: g_Wh[M,256] = A[M,256] @ Bm[256,256] ------------------
// asel: 0 -> Aext (x), 1 -> g_h, 2 -> g_hA ; bsel: 0 -> g_Wc, 1 -> Bext
__global__ void gemm_kernel(const float* __restrict__ Aext,
                            const float* __restrict__ Bext,
                            int asel, int bsel) {
    const float* A  = (asel == 0) ? Aext : (asel == 1 ? g_h : g_hA);
    const float* Bm = (bsel == 0) ? g_Wc : Bext;
    __shared__ __align__(16) float Ast[16][68];   // [k][m], padded
    __shared__ __align__(16) float Bs [16][64];   // [k][n]
    int tid = threadIdx.x;
    int tx = tid & 15, ty = tid >> 4;
    int mbase = blockIdx.y * 64, nbase = blockIdx.x * 64;
    float acc[4][4];
    #pragma unroll
    for (int i = 0; i < 4; i++)
        #pragma unroll
        for (int j = 0; j < 4; j++) acc[i][j] = 0.f;

    int am = tid >> 2, ak = (tid & 3) * 4;
    int bk = tid >> 4, bn = (tid & 15) * 4;

    for (int kk = 0; kk < NF; kk += 16) {
        float4 av = *(const float4*)&A [(size_t)(mbase + am) * NF + kk + ak];
        float4 bv = *(const float4*)&Bm[(size_t)(kk + bk) * NF + nbase + bn];
        Ast[ak + 0][am] = av.x; Ast[ak + 1][am] = av.y;
        Ast[ak + 2][am] = av.z; Ast[ak + 3][am] = av.w;
        *(float4*)&Bs[bk][bn] = bv;
        __syncthreads();
        #pragma unroll
        for (int k = 0; k < 16; k++) {
            float4 a = *(const float4*)&Ast[k][ty * 4];
            float4 b = *(const float4*)&Bs [k][tx * 4];
            acc[0][0] += a.x * b.x; acc[0][1] += a.x * b.y;
            acc[0][2] += a.x * b.z; acc[0][3] += a.x * b.w;
            acc[1][0] += a.y * b.x; acc[1][1] += a.y * b.y;
            acc[1][2] += a.y * b.z; acc[1][3] += a.y * b.w;
            acc[2][0] += a.z * b.x; acc[2][1] += a.z * b.y;
            acc[2][2] += a.z * b.z; acc[2][3] += a.z * b.w;
            acc[3][0] += a.w * b.x; acc[3][1] += a.w * b.y;
            acc[3][2] += a.w * b.z; acc[3][3] += a.w * b.w;
        }
        __syncthreads();
    }
    #pragma unroll
    for (int i = 0; i < 4; i++) {
        *(float4*)&g_Wh[(size_t)(mbase + ty * 4 + i) * NF + nbase + tx * 4] =
            make_float4(acc[i][0], acc[i][1], acc[i][2], acc[i][3]);
    }
}

// ---------------- s1/s2 for the 8-head stage ----------------------------------
__global__ void sheads_kernel(const float* __restrict__ aheads, int l) {
    int w = threadIdx.x >> 5, lane = threadIdx.x & 31;
    int row = blockIdx.x * 8 + w;          // b*NN + n
    int b = row >> 11, n = row & (NN - 1);
    #pragma unroll
    for (int h = 0; h < NH; h++) {
        float v  = g_Wh[(size_t)row * NF + h * NO + lane];
        float a1 = aheads[((size_t)l * NH + h) * 2 * NO + lane];
        float a2 = aheads[((size_t)l * NH + h) * 2 * NO + NO + lane];
        float p1 = v * a1, p2 = v * a2;
        #pragma unroll
        for (int off = 16; off; off >>= 1) {
            p1 += __shfl_xor_sync(0xffffffffu, p1, off);
            p2 += __shfl_xor_sync(0xffffffffu, p2, off);
        }
        if (lane == 0) {
            g_s1[(b * NH + h) * NN + n] = p1;
            g_s2[(b * NH + h) * NN + n] = p2;
        }
    }
}

// ---------------- s1/s2 for the single-head out stage -------------------------
__global__ void sout_kernel(const float* __restrict__ aout, int l) {
    int w = threadIdx.x >> 5, lane = threadIdx.x & 31;
    int row = blockIdx.x * 8 + w;          // b*NN + n
    float p1 = 0.f, p2 = 0.f;
    #pragma unroll
    for (int k = 0; k < NF / 32; k++) {
        float v = g_Wh[(size_t)row * NF + k * 32 + lane];
        p1 += v * aout[(size_t)l * 2 * NF + k * 32 + lane];
        p2 += v * aout[(size_t)l * 2 * NF + NF + k * 32 + lane];
    }
    #pragma unroll
    for (int off = 16; off; off >>= 1) {
        p1 += __shfl_xor_sync(0xffffffffu, p1, off);
        p2 += __shfl_xor_sync(0xffffffffu, p2, off);
    }
    if (lane == 0) { g_s1[row] = p1; g_s2[row] = p2; }
}

// ---------------- per-(b,head) max of s2 (softmax upper bound) ----------------
__global__ void m2_kernel() {
    int s = blockIdx.x;
    __shared__ float sm[256];
    float m = -3.0e38f;
    for (int i = threadIdx.x; i < NN; i += 256)
        m = fmaxf(m, g_s2[(size_t)s * NN + i]);
    sm[threadIdx.x] = m;
    __syncthreads();
    for (int off = 128; off; off >>= 1) {
        if (threadIdx.x < off)
            sm[threadIdx.x] = fmaxf(sm[threadIdx.x], sm[threadIdx.x + off]);
        __syncthreads();
    }
    if (threadIdx.x == 0) g_M2[s] = sm[0];
}

// ---------------- fused attention v3: all 256 cols per block, FFMA2 -----------
// Block: 8 warps x R=4 rows = 32 rows, lane covers 8 columns of one head
// (lane L -> head g=L>>2, sub s=L&3, cols = g*32 + s + 4k, k=0..7).
// acc2[r][k] is a packed f32x2 accumulating even/odd-j partial sums; pk/vj
// halves come straight from the LDS register pairs, so FFMA2 needs no splats.
// Dynamic smem layout (floats):
//   V4  [256][32] float4   : 32768      (o-major, j4 xor-swizzled)
//   ps  [8w][4r][8h][36]   : 9216       (head stride padded -> bank spread)
//   s2s [8][128]           : 1024
//   s1s [32][8]            : 256
//   cis [32][8]            : 256
#define ATTN2_SMEM (43520 * 4)
#define JT2 128

template<int H, int ELU2>
__global__ void __launch_bounds__(256, 1)
attn3_kernel(float* __restrict__ oext, int osel) {
    extern __shared__ float smdyn[];
    float4* V4  = (float4*)smdyn;                  // [o*32 + j4sw]
    float*  psb = smdyn + 32768;
    float*  s2s = smdyn + 32768 + 9216;
    float*  s1s = s2s + 1024;
    float*  cis = s1s + 256;

    float* out = (osel == 0) ? g_hA : (osel == 1 ? g_h : oext);
    int b = blockIdx.z;
    int tid = threadIdx.x;
    int w = tid >> 5, lane = tid & 31;
    int g = lane >> 2, s = lane & 3;
    const int heff = (H == NH) ? 0 : -1;           // marker; real heff below
    int hsel = (H == NH) ? g : 0;
    (void)heff;
    int row0b = blockIdx.x * 32;
    int rowW  = row0b + w * 4;

    // preload s1 / cir (upper bound for softmax shift)
    {
        int rl = tid >> 3, h = tid & 7;
        int hh = (h < H) ? h : 0;
        int sidx = b * H + hh;
        float s1v = g_s1[(size_t)sidx * NN + row0b + rl];
        float t = s1v + g_M2[sidx];
        s1s[rl * 8 + h] = s1v;
        cis[rl * 8 + h] = fmaxf(t, 0.2f * t);
    }

    ull acc2[4][8];
    ull ls2[4];
    const ull zz = 0ull;
    #pragma unroll
    for (int r = 0; r < 4; r++) {
        ls2[r] = zz;
        #pragma unroll
        for (int k = 0; k < 8; k++) acc2[r][k] = zz;
    }

    float* psw = psb + w * 1152;                   // [r*288 + h*36 + j]
    const float* pkbase = psw + hsel * 36;

    for (int jt = 0; jt < NN; jt += JT2) {
        // ---- load V tile transposed (o-major, float4 over j, xor swizzle) ----
        {
            const float* Vb = g_Wh + ((size_t)(b * NN + jt)) * NF + tid;  // col=tid
            int swz = ((tid >> 5) ^ tid) & 7;
            #pragma unroll 4
            for (int j4 = 0; j4 < 32; j4++) {
                float4 v;
                v.x = Vb[(j4 * 4 + 0) * NF];
                v.y = Vb[(j4 * 4 + 1) * NF];
                v.z = Vb[(j4 * 4 + 2) * NF];
                v.w = Vb[(j4 * 4 + 3) * NF];
                V4[tid * 32 + (j4 ^ swz)] = v;
            }
            #pragma unroll
            for (int hh = 0; hh < H; hh++) {
                int h = (tid >> 7) + hh * 2;
                if (h < H)
                    s2s[h * 128 + (tid & 127)] =
                        g_s2[(size_t)(b * H + h) * NN + jt + (tid & 127)];
                if (H == 1) break;
            }
        }
        __syncthreads();

        #pragma unroll
        for (int c = 0; c < 4; c++) {
            // ---- p compute (lane = j within 32-chunk) ----
            unsigned mw[4];
            #pragma unroll
            for (int r = 0; r < 4; r++)
                mw[r] = g_bm[((size_t)(b * NN + rowW + r) << 6) + (jt >> 5) + c];
            #pragma unroll
            for (int h = 0; h < H; h++) {
                float s2v = s2s[h * 128 + c * 32 + lane];
                #pragma unroll
                for (int r = 0; r < 4; r++) {
                    float x = s1s[(w * 4 + r) * 8 + h] + s2v;
                    float e = fmaxf(x, 0.2f * x);
                    float p = ((mw[r] >> lane) & 1u)
                                ? __expf(e - cis[(w * 4 + r) * 8 + h]) : 0.f;
                    psw[r * 288 + h * 36 + lane] = p;
                }
            }
            __syncwarp();

            // ---- micro-GEMM: P[4x32] @ V[32x(8 cols/lane)], f32x2 packed ----
            #pragma unroll
            for (int k4 = 0; k4 < 8; k4++) {
                ull pkl[4], pkh[4];
                #pragma unroll
                for (int r = 0; r < 4; r++) {
                    const float* pp = pkbase + r * 288 + k4 * 4;
                    pkl[r] = *(const ull*)pp;
                    pkh[r] = *(const ull*)(pp + 2);
                    fadd2(ls2[r], pkl[r]);
                    fadd2(ls2[r], pkh[r]);
                }
                #pragma unroll
                for (int k = 0; k < 8; k++) {
                    int o = g * 32 + s + 4 * k;
                    float4 vj = V4[o * 32 + ((c * 8 + k4) ^ ((g ^ o) & 7))];
                    ull vl = pack2(vj.x, vj.y);
                    ull vh = pack2(vj.z, vj.w);
                    #pragma unroll
                    for (int r = 0; r < 4; r++) {
                        ffma2(acc2[r][k], pkl[r], vl);
                        ffma2(acc2[r][k], pkh[r], vh);
                    }
                }
            }
            __syncwarp();
        }
        __syncthreads();
    }

    // ---- epilogue: normalize, elu, store ----
    #pragma unroll
    for (int r = 0; r < 4; r++) {
        float2 lp = unpack2(ls2[r]);
        float inv = 1.0f / (lp.x + lp.y);
        float* op = out + ((size_t)(b * NN + rowW + r)) * NF;
        #pragma unroll
        for (int k = 0; k < 8; k++) {
            float2 ap = unpack2(acc2[r][k]);
            float v = (ap.x + ap.y) * inv;
            v = (v > 0.f) ? v : (__expf(v) - 1.f);
            if (ELU2) v = (v > 0.f) ? v : (__expf(v) - 1.f);
            op[g * 32 + s + 4 * k] = v;
        }
    }
}

// ---------------- launch ------------------------------------------------------
extern "C" void kernel_launch(void* const* d_in, const int* in_sizes, int n_in,
                              void* d_out, int out_size) {
    const float* x       = (const float*)d_in[0];
    const int*   adj     = (const int*)  d_in[1];
    const float* W_heads = (const float*)d_in[2];
    const float* a_heads = (const float*)d_in[3];
    const float* W_out   = (const float*)d_in[4];
    const float* a_out   = (const float*)d_in[5];
    float* out = (float*)d_out;

    cudaFuncSetAttribute(attn3_kernel<NH, 0>,
                         cudaFuncAttributeMaxDynamicSharedMemorySize,
                         ATTN2_SMEM);
    cudaFuncSetAttribute(attn3_kernel<1, 1>,
                         cudaFuncAttributeMaxDynamicSharedMemorySize,
                         ATTN2_SMEM);

    bm_kernel<<<NB * NN * 64 / 8, 256>>>(adj);

    for (int l = 0; l < 3; l++) {
        // ---- stage A: 8-head GAT ----
        pack_kernel<<<NF, NF>>>(W_heads, l);
        gemm_kernel<<<dim3(4, NB * NN / 64), 256>>>(l == 0 ? x : nullptr, nullptr,
                                                    l == 0 ? 0 : 1, 0);
        sheads_kernel<<<NB * NN / 8, 256>>>(a_heads, l);
        m2_kernel<<<NB * NH, 256>>>();
        attn3_kernel<NH, 0><<<dim3(NN / 32, 1, NB), 256, ATTN2_SMEM>>>(
            nullptr, 0);

        // ---- stage B: single-head out GAT (+extra elu) ----
        gemm_kernel<<<dim3(4, NB * NN / 64), 256>>>(nullptr,
                                                    W_out + (size_t)l * NF * NF,
                                                    2, 1);
        sout_kernel<<<NB * NN / 8, 256>>>(a_out, l);
        m2_kernel<<<NB, 256>>>();
        attn3_kernel<1, 1><<<dim3(NN / 32, 1, NB), 256, ATTN2_SMEM>>>(
            l == 2 ? out : nullptr, l == 2 ? 2 : 1);
    }
}

// round 7
// speedup vs baseline: 1.0232x; 1.0232x over previous
#include <cuda_runtime.h>
#include <cuda_bf16.h>

#define NB 2
#define NN 2048
#define NF 256
#define NH 8
#define NO 32

// ---------------- scratch (device globals; no allocation allowed) -------------
__device__ __align__(128) float    g_h [NB*NN*NF];   // layer input / stage-B output
__device__ __align__(128) float    g_hA[NB*NN*NF];   // stage-A attention output
__device__ __align__(128) float    g_Wh[NB*NN*NF];   // projected features (V)
__device__ __align__(128) float    g_Wc[NF*NF];      // packed per-layer head weights
__device__ __align__(128) float    g_s1[NB*NH*NN];
__device__ __align__(128) float    g_s2[NB*NH*NN];
__device__             float       g_M2[NB*NH];
__device__ __align__(128) unsigned g_bm[NB*NN*(NN/32)];  // adjacency bitmask

// ---------------- adjacency -> bitmask (runs once) ----------------------------
__global__ void bm_kernel(const int* __restrict__ adj) {
    int wid  = blockIdx.x * 8 + (threadIdx.x >> 5);
    int lane = threadIdx.x & 31;
    int word = wid & 63;
    int row  = wid >> 6;                       // b*NN + i
    int j = word * 32 + lane;
    int a = adj[(size_t)row * NN + j];
    unsigned bits = __ballot_sync(0xffffffffu, a != 0);
    if (lane == 0) g_bm[wid] = bits;
}

// ---------------- pack W_heads[l] into [F, H*O] column-major-by-head ----------
__global__ void pack_kernel(const float* __restrict__ Wheads, int l) {
    int f = blockIdx.x, c = threadIdx.x;
    g_Wc[f * NF + c] =
        Wheads[(((size_t)l * NH + (c >> 5)) * NF + f) * NO + (c & 31)];
}

// ---------------- GEMM: g_Wh[M,256] = A[M,256] @ Bm[256,256] ------------------
// asel: 0 -> Aext (x), 1 -> g_h, 2 -> g_hA ; bsel: 0 -> g_Wc, 1 -> Bext
__global__ void gemm_kernel(const float* __restrict__ Aext,
                            const float* __restrict__ Bext,
                            int asel, int bsel) {
    const float* A  = (asel == 0) ? Aext : (asel == 1 ? g_h : g_hA);
    const float* Bm = (bsel == 0) ? g_Wc : Bext;
    __shared__ __align__(16) float Ast[16][68];   // [k][m], padded
    __shared__ __align__(16) float Bs [16][64];   // [k][n]
    int tid = threadIdx.x;
    int tx = tid & 15, ty = tid >> 4;
    int mbase = blockIdx.y * 64, nbase = blockIdx.x * 64;
    float acc[4][4];
    #pragma unroll
    for (int i = 0; i < 4; i++)
        #pragma unroll
        for (int j = 0; j < 4; j++) acc[i][j] = 0.f;

    int am = tid >> 2, ak = (tid & 3) * 4;
    int bk = tid >> 4, bn = (tid & 15) * 4;

    for (int kk = 0; kk < NF; kk += 16) {
        float4 av = *(const float4*)&A [(size_t)(mbase + am) * NF + kk + ak];
        float4 bv = *(const float4*)&Bm[(size_t)(kk + bk) * NF + nbase + bn];
        Ast[ak + 0][am] = av.x; Ast[ak + 1][am] = av.y;
        Ast[ak + 2][am] = av.z; Ast[ak + 3][am] = av.w;
        *(float4*)&Bs[bk][bn] = bv;
        __syncthreads();
        #pragma unroll
        for (int k = 0; k < 16; k++) {
            float4 a = *(const float4*)&Ast[k][ty * 4];
            float4 b = *(const float4*)&Bs [k][tx * 4];
            acc[0][0] += a.x * b.x; acc[0][1] += a.x * b.y;
            acc[0][2] += a.x * b.z; acc[0][3] += a.x * b.w;
            acc[1][0] += a.y * b.x; acc[1][1] += a.y * b.y;
            acc[1][2] += a.y * b.z; acc[1][3] += a.y * b.w;
            acc[2][0] += a.z * b.x; acc[2][1] += a.z * b.y;
            acc[2][2] += a.z * b.z; acc[2][3] += a.z * b.w;
            acc[3][0] += a.w * b.x; acc[3][1] += a.w * b.y;
            acc[3][2] += a.w * b.z; acc[3][3] += a.w * b.w;
        }
        __syncthreads();
    }
    #pragma unroll
    for (int i = 0; i < 4; i++) {
        *(float4*)&g_Wh[(size_t)(mbase + ty * 4 + i) * NF + nbase + tx * 4] =
            make_float4(acc[i][0], acc[i][1], acc[i][2], acc[i][3]);
    }
}

// ---------------- s1/s2 for the 8-head stage ----------------------------------
__global__ void sheads_kernel(const float* __restrict__ aheads, int l) {
    int w = threadIdx.x >> 5, lane = threadIdx.x & 31;
    int row = blockIdx.x * 8 + w;          // b*NN + n
    int b = row >> 11, n = row & (NN - 1);
    #pragma unroll
    for (int h = 0; h < NH; h++) {
        float v  = g_Wh[(size_t)row * NF + h * NO + lane];
        float a1 = aheads[((size_t)l * NH + h) * 2 * NO + lane];
        float a2 = aheads[((size_t)l * NH + h) * 2 * NO + NO + lane];
        float p1 = v * a1, p2 = v * a2;
        #pragma unroll
        for (int off = 16; off; off >>= 1) {
            p1 += __shfl_xor_sync(0xffffffffu, p1, off);
            p2 += __shfl_xor_sync(0xffffffffu, p2, off);
        }
        if (lane == 0) {
            g_s1[(b * NH + h) * NN + n] = p1;
            g_s2[(b * NH + h) * NN + n] = p2;
        }
    }
}

// ---------------- s1/s2 for the single-head out stage -------------------------
__global__ void sout_kernel(const float* __restrict__ aout, int l) {
    int w = threadIdx.x >> 5, lane = threadIdx.x & 31;
    int row = blockIdx.x * 8 + w;          // b*NN + n
    float p1 = 0.f, p2 = 0.f;
    #pragma unroll
    for (int k = 0; k < NF / 32; k++) {
        float v = g_Wh[(size_t)row * NF + k * 32 + lane];
        p1 += v * aout[(size_t)l * 2 * NF + k * 32 + lane];
        p2 += v * aout[(size_t)l * 2 * NF + NF + k * 32 + lane];
    }
    #pragma unroll
    for (int off = 16; off; off >>= 1) {
        p1 += __shfl_xor_sync(0xffffffffu, p1, off);
        p2 += __shfl_xor_sync(0xffffffffu, p2, off);
    }
    if (lane == 0) { g_s1[row] = p1; g_s2[row] = p2; }
}

// ---------------- per-(b,head) max of s2 (softmax upper bound) ----------------
__global__ void m2_kernel() {
    int s = blockIdx.x;
    __shared__ float sm[256];
    float m = -3.0e38f;
    for (int i = threadIdx.x; i < NN; i += 256)
        m = fmaxf(m, g_s2[(size_t)s * NN + i]);
    sm[threadIdx.x] = m;
    __syncthreads();
    for (int off = 128; off; off >>= 1) {
        if (threadIdx.x < off)
            sm[threadIdx.x] = fmaxf(sm[threadIdx.x], sm[threadIdx.x + off]);
        __syncthreads();
    }
    if (threadIdx.x == 0) g_M2[s] = sm[0];
}

// ---------------- fused masked-softmax attention + P@V + elu -----------------
// v4 = round-4 v1 structure with RPW 4 -> 8 (vj LDS amortized over 2x FFMAs).
// grid (NN/64, 8, NB), block 256 (8 warps x 8 rows/warp, lane = output column)
// y = head (stage A) or o-chunk (stage B). V = g_Wh columns [y*32, y*32+32).
#define JT  128
#define RPW 8
#define AW  8

__global__ void __launch_bounds__(256)
attn_kernel(float* __restrict__ oext, int osel,
            int spb, int symul, int elu2) {
    __shared__ __align__(16) float Vst[NO * JT];        // transposed, xor-swizzled float4s
    __shared__             float s2s[JT];
    __shared__ __align__(16) float ps[AW][RPW][32];

    float* out = (osel == 0) ? g_hA : (osel == 1 ? g_h : oext);
    int b = blockIdx.z, y = blockIdx.y;
    int w = threadIdx.x >> 5, lane = threadIdx.x & 31;
    int vb = y * NO;
    int sidx = b * spb + y * symul;
    const float* s1p = g_s1 + (size_t)sidx * NN;
    const float* s2p = g_s2 + (size_t)sidx * NN;
    float m2 = g_M2[sidx];
    int row0 = blockIdx.x * (AW * RPW) + w * RPW;

    float s1r[RPW], cir[RPW], acc[RPW], lsum[RPW];
    #pragma unroll
    for (int r = 0; r < RPW; r++) {
        s1r[r] = s1p[row0 + r];
        float t = s1r[r] + m2;
        cir[r] = fmaxf(t, 0.2f * t);       // upper bound on all masked logits
        acc[r] = 0.f; lsum[r] = 0.f;
    }
    const unsigned* bmb = g_bm + ((size_t)(b * NN + row0) << 6);
    const float* Vbase = g_Wh + vb;

    for (int jt = 0; jt < NN; jt += JT) {
        {   // load V tile transposed [o][j] with float4 xor-swizzle, + s2 tile
            int tid = threadIdx.x;
            #pragma unroll
            for (int pass = 0; pass < 4; pass++) {
                int idx = tid + pass * 256;
                int o = idx & 31, j4 = idx >> 5;        // j4 in 0..31
                int jg = jt + j4 * 4;
                float4 v;
                v.x = Vbase[(size_t)(b * NN + jg + 0) * NF + o];
                v.y = Vbase[(size_t)(b * NN + jg + 1) * NF + o];
                v.z = Vbase[(size_t)(b * NN + jg + 2) * NF + o];
                v.w = Vbase[(size_t)(b * NN + jg + 3) * NF + o];
                ((float4*)Vst)[o * 32 + (j4 ^ (o & 7))] = v;
            }
            if (tid < JT) s2s[tid] = s2p[jt + tid];
        }
        __syncthreads();

        #pragma unroll
        for (int c = 0; c < JT / 32; c++) {
            float s2v = s2s[c * 32 + lane];
            #pragma unroll
            for (int r = 0; r < RPW; r++) {
                unsigned mw = __ldg(&bmb[((size_t)r << 6) + (jt >> 5) + c]);
                float x = s1r[r] + s2v;
                float e = fmaxf(x, 0.2f * x);           // leakyrelu(0.2)
                float p = ((mw >> lane) & 1u) ? __expf(e - cir[r]) : 0.f;
                lsum[r] += p;
                ps[w][r][lane] = p;
            }
            __syncwarp();
            #pragma unroll
            for (int k4 = 0; k4 < 8; k4++) {
                float4 vj = ((const float4*)Vst)[lane * 32 + ((c * 8 + k4) ^ (lane & 7))];
                #pragma unroll
                for (int r = 0; r < RPW; r++) {
                    float4 pk = *(const float4*)&ps[w][r][k4 * 4];
                    acc[r] += pk.x * vj.x + pk.y * vj.y + pk.z * vj.z + pk.w * vj.w;
                }
            }
            __syncwarp();
        }
        __syncthreads();
    }

    #pragma unroll
    for (int r = 0; r < RPW; r++) {
        float l = lsum[r];
        #pragma unroll
        for (int off = 16; off; off >>= 1)
            l += __shfl_xor_sync(0xffffffffu, l, off);
        float v = acc[r] / l;
        v = (v > 0.f) ? v : (__expf(v) - 1.f);          // elu
        if (elu2) v = (v > 0.f) ? v : (__expf(v) - 1.f); // second elu (out stage)
        out[(size_t)(b * NN + row0 + r) * NF + vb + lane] = v;
    }
}

// ---------------- launch ------------------------------------------------------
extern "C" void kernel_launch(void* const* d_in, const int* in_sizes, int n_in,
                              void* d_out, int out_size) {
    const float* x       = (const float*)d_in[0];
    const int*   adj     = (const int*)  d_in[1];
    const float* W_heads = (const float*)d_in[2];
    const float* a_heads = (const float*)d_in[3];
    const float* W_out   = (const float*)d_in[4];
    const float* a_out   = (const float*)d_in[5];
    float* out = (float*)d_out;

    bm_kernel<<<NB * NN * 64 / 8, 256>>>(adj);

    for (int l = 0; l < 3; l++) {
        // ---- stage A: 8-head GAT ----
        pack_kernel<<<NF, NF>>>(W_heads, l);
        gemm_kernel<<<dim3(4, NB * NN / 64), 256>>>(l == 0 ? x : nullptr, nullptr,
                                                    l == 0 ? 0 : 1, 0);
        sheads_kernel<<<NB * NN / 8, 256>>>(a_heads, l);
        m2_kernel<<<NB * NH, 256>>>();
        attn_kernel<<<dim3(NN / (AW * RPW), 8, NB), 256>>>(nullptr, 0, NH, 1, 0);

        // ---- stage B: single-head out GAT (+extra elu) ----
        gemm_kernel<<<dim3(4, NB * NN / 64), 256>>>(nullptr,
                                                    W_out + (size_t)l * NF * NF,
                                                    2, 1);
        sout_kernel<<<NB * NN / 8, 256>>>(a_out, l);
        m2_kernel<<<NB, 256>>>();
        attn_kernel<<<dim3(NN / (AW * RPW), 8, NB), 256>>>(l == 2 ? out : nullptr,
                                                           l == 2 ? 2 : 1, 1, 0, 1);
    }
}

// round 8
// speedup vs baseline: 1.1496x; 1.1235x over previous
#include <cuda_runtime.h>
#include <cuda_bf16.h>

#define NB 2
#define NN 2048
#define NF 256
#define NH 8
#define NO 32

typedef unsigned long long ull;

// ---------------- f32x2 packed-math helpers (sm_103a FFMA2 path) --------------
__device__ __forceinline__ void ffma2(ull& d, ull a, ull b) {
    asm("fma.rn.f32x2 %0, %1, %2, %0;" : "+l"(d) : "l"(a), "l"(b));
}
__device__ __forceinline__ float2 unpack2(ull v) {
    float2 r;
    asm("mov.b64 {%0, %1}, %2;" : "=f"(r.x), "=f"(r.y) : "l"(v));
    return r;
}

// ---------------- scratch (device globals; no allocation allowed) -------------
__device__ __align__(128) float    g_h [NB*NN*NF];   // layer input / stage-B output
__device__ __align__(128) float    g_hA[NB*NN*NF];   // stage-A attention output
__device__ __align__(128) float    g_Wh[NB*NN*NF];   // projected features (V)
__device__ __align__(128) float    g_Wc[NF*NF];      // packed per-layer head weights
__device__ __align__(128) float    g_s1[NB*NH*NN];
__device__ __align__(128) float    g_s2[NB*NH*NN];
__device__             float       g_M2[NB*NH];
__device__ __align__(128) unsigned g_bm[NB*NN*(NN/32)];  // adjacency bitmask

// ---------------- adjacency -> bitmask (runs once) ----------------------------
__global__ void bm_kernel(const int* __restrict__ adj) {
    int wid  = blockIdx.x * 8 + (threadIdx.x >> 5);
    int lane = threadIdx.x & 31;
    int word = wid & 63;
    int row  = wid >> 6;                       // b*NN + i
    int j = word * 32 + lane;
    int a = adj[(size_t)row * NN + j];
    unsigned bits = __ballot_sync(0xffffffffu, a != 0);
    if (lane == 0) g_bm[wid] = bits;
}

// ---------------- pack W_heads[l] into [F, H*O] column-major-by-head ----------
__global__ void pack_kernel(const float* __restrict__ Wheads, int l) {
    int f = blockIdx.x, c = threadIdx.x;
    g_Wc[f * NF + c] =
        Wheads[(((size_t)l * NH + (c >> 5)) * NF + f) * NO + (c & 31)];
}

// ---------------- GEMM: g_Wh[M,256] = A[M,256] @ Bm[256,256] ------------------
// asel: 0 -> Aext (x), 1 -> g_h, 2 -> g_hA ; bsel: 0 -> g_Wc, 1 -> Bext
__global__ void gemm_kernel(const float* __restrict__ Aext,
                            const float* __restrict__ Bext,
                            int asel, int bsel) {
    const float* A  = (asel == 0) ? Aext : (asel == 1 ? g_h : g_hA);
    const float* Bm = (bsel == 0) ? g_Wc : Bext;
    __shared__ __align__(16) float Ast[16][68];   // [k][m], padded
    __shared__ __align__(16) float Bs [16][64];   // [k][n]
    int tid = threadIdx.x;
    int tx = tid & 15, ty = tid >> 4;
    int mbase = blockIdx.y * 64, nbase = blockIdx.x * 64;
    float acc[4][4];
    #pragma unroll
    for (int i = 0; i < 4; i++)
        #pragma unroll
        for (int j = 0; j < 4; j++) acc[i][j] = 0.f;

    int am = tid >> 2, ak = (tid & 3) * 4;
    int bk = tid >> 4, bn = (tid & 15) * 4;

    for (int kk = 0; kk < NF; kk += 16) {
        float4 av = *(const float4*)&A [(size_t)(mbase + am) * NF + kk + ak];
        float4 bv = *(const float4*)&Bm[(size_t)(kk + bk) * NF + nbase + bn];
        Ast[ak + 0][am] = av.x; Ast[ak + 1][am] = av.y;
        Ast[ak + 2][am] = av.z; Ast[ak + 3][am] = av.w;
        *(float4*)&Bs[bk][bn] = bv;
        __syncthreads();
        #pragma unroll
        for (int k = 0; k < 16; k++) {
            float4 a = *(const float4*)&Ast[k][ty * 4];
            float4 b = *(const float4*)&Bs [k][tx * 4];
            acc[0][0] += a.x * b.x; acc[0][1] += a.x * b.y;
            acc[0][2] += a.x * b.z; acc[0][3] += a.x * b.w;
            acc[1][0] += a.y * b.x; acc[1][1] += a.y * b.y;
            acc[1][2] += a.y * b.z; acc[1][3] += a.y * b.w;
            acc[2][0] += a.z * b.x; acc[2][1] += a.z * b.y;
            acc[2][2] += a.z * b.z; acc[2][3] += a.z * b.w;
            acc[3][0] += a.w * b.x; acc[3][1] += a.w * b.y;
            acc[3][2] += a.w * b.z; acc[3][3] += a.w * b.w;
        }
        __syncthreads();
    }
    #pragma unroll
    for (int i = 0; i < 4; i++) {
        *(float4*)&g_Wh[(size_t)(mbase + ty * 4 + i) * NF + nbase + tx * 4] =
            make_float4(acc[i][0], acc[i][1], acc[i][2], acc[i][3]);
    }
}

// ---------------- s1/s2 for the 8-head stage ----------------------------------
__global__ void sheads_kernel(const float* __restrict__ aheads, int l) {
    int w = threadIdx.x >> 5, lane = threadIdx.x & 31;
    int row = blockIdx.x * 8 + w;          // b*NN + n
    int b = row >> 11, n = row & (NN - 1);
    #pragma unroll
    for (int h = 0; h < NH; h++) {
        float v  = g_Wh[(size_t)row * NF + h * NO + lane];
        float a1 = aheads[((size_t)l * NH + h) * 2 * NO + lane];
        float a2 = aheads[((size_t)l * NH + h) * 2 * NO + NO + lane];
        float p1 = v * a1, p2 = v * a2;
        #pragma unroll
        for (int off = 16; off; off >>= 1) {
            p1 += __shfl_xor_sync(0xffffffffu, p1, off);
            p2 += __shfl_xor_sync(0xffffffffu, p2, off);
        }
        if (lane == 0) {
            g_s1[(b * NH + h) * NN + n] = p1;
            g_s2[(b * NH + h) * NN + n] = p2;
        }
    }
}

// ---------------- s1/s2 for the single-head out stage -------------------------
__global__ void sout_kernel(const float* __restrict__ aout, int l) {
    int w = threadIdx.x >> 5, lane = threadIdx.x & 31;
    int row = blockIdx.x * 8 + w;          // b*NN + n
    float p1 = 0.f, p2 = 0.f;
    #pragma unroll
    for (int k = 0; k < NF / 32; k++) {
        float v = g_Wh[(size_t)row * NF + k * 32 + lane];
        p1 += v * aout[(size_t)l * 2 * NF + k * 32 + lane];
        p2 += v * aout[(size_t)l * 2 * NF + NF + k * 32 + lane];
    }
    #pragma unroll
    for (int off = 16; off; off >>= 1) {
        p1 += __shfl_xor_sync(0xffffffffu, p1, off);
        p2 += __shfl_xor_sync(0xffffffffu, p2, off);
    }
    if (lane == 0) { g_s1[row] = p1; g_s2[row] = p2; }
}

// ---------------- per-(b,head) max of s2 (softmax upper bound) ----------------
__global__ void m2_kernel() {
    int s = blockIdx.x;
    __shared__ float sm[256];
    float m = -3.0e38f;
    for (int i = threadIdx.x; i < NN; i += 256)
        m = fmaxf(m, g_s2[(size_t)s * NN + i]);
    sm[threadIdx.x] = m;
    __syncthreads();
    for (int off = 128; off; off >>= 1) {
        if (threadIdx.x < off)
            sm[threadIdx.x] = fmaxf(sm[threadIdx.x], sm[threadIdx.x + off]);
        __syncthreads();
    }
    if (threadIdx.x == 0) g_M2[s] = sm[0];
}

// ---------------- fused masked-softmax attention + P@V + elu -----------------
// v5 = round-4 v1 structure EXACTLY, with the micro-GEMM switched to packed
// fma.rn.f32x2 (even/odd-j halves in one accumulator) -> half the fma-pipe
// instructions. Everything else (RPW=4, smem, grid, syncs) unchanged.
// grid (NN/32, 8, NB), block 256 (8 warps x 4 rows/warp, lane = output column)
#define JT  128
#define RPW 4
#define AW  8

__global__ void __launch_bounds__(256)
attn_kernel(float* __restrict__ oext, int osel,
            int spb, int symul, int elu2) {
    __shared__ __align__(16) float Vst[NO * JT];        // transposed, xor-swizzled float4s
    __shared__             float s2s[JT];
    __shared__ __align__(16) float ps[AW][RPW][32];

    float* out = (osel == 0) ? g_hA : (osel == 1 ? g_h : oext);
    int b = blockIdx.z, y = blockIdx.y;
    int w = threadIdx.x >> 5, lane = threadIdx.x & 31;
    int vb = y * NO;
    int sidx = b * spb + y * symul;
    const float* s1p = g_s1 + (size_t)sidx * NN;
    const float* s2p = g_s2 + (size_t)sidx * NN;
    float m2 = g_M2[sidx];
    int row0 = blockIdx.x * (AW * RPW) + w * RPW;

    float s1r[RPW], cir[RPW], lsum[RPW];
    ull acc2[RPW];
    const unsigned* bmr[RPW];
    #pragma unroll
    for (int r = 0; r < RPW; r++) {
        s1r[r] = s1p[row0 + r];
        float t = s1r[r] + m2;
        cir[r] = fmaxf(t, 0.2f * t);       // upper bound on all masked logits
        acc2[r] = 0ull; lsum[r] = 0.f;
        bmr[r] = g_bm + ((size_t)(b * NN + row0 + r) << 6);
    }
    const float* Vbase = g_Wh + vb;

    for (int jt = 0; jt < NN; jt += JT) {
        {   // load V tile transposed [o][j] with float4 xor-swizzle, + s2 tile
            int tid = threadIdx.x;
            #pragma unroll
            for (int pass = 0; pass < 4; pass++) {
                int idx = tid + pass * 256;
                int o = idx & 31, j4 = idx >> 5;        // j4 in 0..31
                int jg = jt + j4 * 4;
                float4 v;
                v.x = Vbase[(size_t)(b * NN + jg + 0) * NF + o];
                v.y = Vbase[(size_t)(b * NN + jg + 1) * NF + o];
                v.z = Vbase[(size_t)(b * NN + jg + 2) * NF + o];
                v.w = Vbase[(size_t)(b * NN + jg + 3) * NF + o];
                ((float4*)Vst)[o * 32 + (j4 ^ (o & 7))] = v;
            }
            if (tid < JT) s2s[tid] = s2p[jt + tid];
        }
        __syncthreads();

        #pragma unroll
        for (int c = 0; c < JT / 32; c++) {
            float s2v = s2s[c * 32 + lane];
            #pragma unroll
            for (int r = 0; r < RPW; r++) {
                unsigned mw = __ldg(&bmr[r][(jt >> 5) + c]);
                float x = s1r[r] + s2v;
                float e = fmaxf(x, 0.2f * x);           // leakyrelu(0.2)
                float p = ((mw >> lane) & 1u) ? __expf(e - cir[r]) : 0.f;
                lsum[r] += p;
                ps[w][r][lane] = p;
            }
            __syncwarp();
            #pragma unroll
            for (int k4 = 0; k4 < 8; k4++) {
                const ull* vp = (const ull*)
                    &((const float4*)Vst)[lane * 32 + ((c * 8 + k4) ^ (lane & 7))];
                ull vl = vp[0], vh = vp[1];
                #pragma unroll
                for (int r = 0; r < RPW; r++) {
                    const ull* pp = (const ull*)&ps[w][r][k4 * 4];
                    ffma2(acc2[r], pp[0], vl);
                    ffma2(acc2[r], pp[1], vh);
                }
            }
            __syncwarp();
        }
        __syncthreads();
    }

    #pragma unroll
    for (int r = 0; r < RPW; r++) {
        float l = lsum[r];
        #pragma unroll
        for (int off = 16; off; off >>= 1)
            l += __shfl_xor_sync(0xffffffffu, l, off);
        float2 ap = unpack2(acc2[r]);
        float v = (ap.x + ap.y) / l;
        v = (v > 0.f) ? v : (__expf(v) - 1.f);          // elu
        if (elu2) v = (v > 0.f) ? v : (__expf(v) - 1.f); // second elu (out stage)
        out[(size_t)(b * NN + row0 + r) * NF + vb + lane] = v;
    }
}

// ---------------- launch ------------------------------------------------------
extern "C" void kernel_launch(void* const* d_in, const int* in_sizes, int n_in,
                              void* d_out, int out_size) {
    const float* x       = (const float*)d_in[0];
    const int*   adj     = (const int*)  d_in[1];
    const float* W_heads = (const float*)d_in[2];
    const float* a_heads = (const float*)d_in[3];
    const float* W_out   = (const float*)d_in[4];
    const float* a_out   = (const float*)d_in[5];
    float* out = (float*)d_out;

    bm_kernel<<<NB * NN * 64 / 8, 256>>>(adj);

    for (int l = 0; l < 3; l++) {
        // ---- stage A: 8-head GAT ----
        pack_kernel<<<NF, NF>>>(W_heads, l);
        gemm_kernel<<<dim3(4, NB * NN / 64), 256>>>(l == 0 ? x : nullptr, nullptr,
                                                    l == 0 ? 0 : 1, 0);
        sheads_kernel<<<NB * NN / 8, 256>>>(a_heads, l);
        m2_kernel<<<NB * NH, 256>>>();
        attn_kernel<<<dim3(NN / (AW * RPW), 8, NB), 256>>>(nullptr, 0, NH, 1, 0);

        // ---- stage B: single-head out GAT (+extra elu) ----
        gemm_kernel<<<dim3(4, NB * NN / 64), 256>>>(nullptr,
                                                    W_out + (size_t)l * NF * NF,
                                                    2, 1);
        sout_kernel<<<NB * NN / 8, 256>>>(a_out, l);
        m2_kernel<<<NB, 256>>>();
        attn_kernel<<<dim3(NN / (AW * RPW), 8, NB), 256>>>(l == 2 ? out : nullptr,
                                                           l == 2 ? 2 : 1, 1, 0, 1);
    }
}

// round 10
// speedup vs baseline: 1.1557x; 1.0053x over previous
#include <cuda_runtime.h>
#include <cuda_bf16.h>

#define NB 2
#define NN 2048
#define NF 256
#define NH 8
#define NO 32

typedef unsigned long long ull;

// ---------------- f32x2 packed-math helpers (sm_103a FFMA2 path) --------------
__device__ __forceinline__ void ffma2(ull& d, ull a, ull b) {
    asm("fma.rn.f32x2 %0, %1, %2, %0;" : "+l"(d) : "l"(a), "l"(b));
}
__device__ __forceinline__ float2 unpack2(ull v) {
    float2 r;
    asm("mov.b64 {%0, %1}, %2;" : "=f"(r.x), "=f"(r.y) : "l"(v));
    return r;
}

// ---------------- cp.async helpers --------------------------------------------
__device__ __forceinline__ void cp16(const void* smem_dst, const void* gsrc) {
    unsigned d = (unsigned)__cvta_generic_to_shared(smem_dst);
    asm volatile("cp.async.cg.shared.global [%0], [%1], 16;" :: "r"(d), "l"(gsrc));
}
#define CP_COMMIT() asm volatile("cp.async.commit_group;")
#define CP_WAIT0()  asm volatile("cp.async.wait_group 0;")
#define CP_WAIT1()  asm volatile("cp.async.wait_group 1;")

// ---------------- scratch (device globals; no allocation allowed) -------------
__device__ __align__(128) float    g_h  [NB*NN*NF];  // layer input / stage-B output
__device__ __align__(128) float    g_hA [NB*NN*NF];  // stage-A attention output
__device__ __align__(128) float    g_Wh [NB*NN*NF];  // projected features, row-major
__device__ __align__(128) float    g_WhT[NB*NF*NN];  // projected features, col-major
__device__ __align__(128) float    g_s1[NB*NH*NN];
__device__ __align__(128) float    g_s2[NB*NH*NN];
__device__ __align__(128) unsigned g_bm[NB*NN*(NN/32)];  // adjacency bitmask

// ---------------- adjacency -> bitmask (runs once) ----------------------------
__global__ void bm_kernel(const int* __restrict__ adj) {
    int wid  = blockIdx.x * 8 + (threadIdx.x >> 5);
    int lane = threadIdx.x & 31;
    int word = wid & 63;
    int row  = wid >> 6;                       // b*NN + i
    int j = word * 32 + lane;
    int a = adj[(size_t)row * NN + j];
    unsigned bits = __ballot_sync(0xffffffffu, a != 0);
    if (lane == 0) g_bm[wid] = bits;
}

// ---------------- GEMM: Wh/WhT = A[M,256] @ B[256,256] ------------------------
// asel: 0 -> Aext (x), 1 -> g_h, 2 -> g_hA
// bmode 0: B = W_heads[l] head-packed on the fly; bmode 1: B = Bsrc (plain)
__global__ void gemm_kernel(const float* __restrict__ Aext,
                            const float* __restrict__ Bsrc,
                            int asel, int bmode) {
    const float* A = (asel == 0) ? Aext : (asel == 1 ? g_h : g_hA);
    __shared__ __align__(16) float Ast[16][68];   // [k][m], padded
    __shared__ __align__(16) float Bs [16][64];   // [k][n]
    int tid = threadIdx.x;
    int tx = tid & 15, ty = tid >> 4;
    int mbase = blockIdx.y * 64, nbase = blockIdx.x * 64;
    float acc[4][4];
    #pragma unroll
    for (int i = 0; i < 4; i++)
        #pragma unroll
        for (int j = 0; j < 4; j++) acc[i][j] = 0.f;

    int am = tid >> 2, ak = (tid & 3) * 4;
    int bk = tid >> 4, bn = (tid & 15) * 4;
    int c0 = nbase + bn, hh = c0 >> 5, cc = c0 & 31;

    for (int kk = 0; kk < NF; kk += 16) {
        float4 av = *(const float4*)&A[(size_t)(mbase + am) * NF + kk + ak];
        float4 bv;
        if (bmode == 0)   // W_heads[l][h][f][o] with h=c>>5, o=c&31 (cc mult of 4)
            bv = *(const float4*)&Bsrc[((size_t)hh * NF + kk + bk) * NO + cc];
        else
            bv = *(const float4*)&Bsrc[(size_t)(kk + bk) * NF + c0];
        Ast[ak + 0][am] = av.x; Ast[ak + 1][am] = av.y;
        Ast[ak + 2][am] = av.z; Ast[ak + 3][am] = av.w;
        *(float4*)&Bs[bk][bn] = bv;
        __syncthreads();
        #pragma unroll
        for (int k = 0; k < 16; k++) {
            float4 a = *(const float4*)&Ast[k][ty * 4];
            float4 b = *(const float4*)&Bs [k][tx * 4];
            acc[0][0] += a.x * b.x; acc[0][1] += a.x * b.y;
            acc[0][2] += a.x * b.z; acc[0][3] += a.x * b.w;
            acc[1][0] += a.y * b.x; acc[1][1] += a.y * b.y;
            acc[1][2] += a.y * b.z; acc[1][3] += a.y * b.w;
            acc[2][0] += a.z * b.x; acc[2][1] += a.z * b.y;
            acc[2][2] += a.z * b.z; acc[2][3] += a.z * b.w;
            acc[3][0] += a.w * b.x; acc[3][1] += a.w * b.y;
            acc[3][2] += a.w * b.z; acc[3][3] += a.w * b.w;
        }
        __syncthreads();
    }
    int bb = mbase >> 11, rowb = mbase & (NN - 1);
    #pragma unroll
    for (int i = 0; i < 4; i++) {
        *(float4*)&g_Wh[(size_t)(mbase + ty * 4 + i) * NF + nbase + tx * 4] =
            make_float4(acc[i][0], acc[i][1], acc[i][2], acc[i][3]);
    }
    // transposed store: thread holds a 4x4 block; write 4 float4s along n (col j)
    #pragma unroll
    for (int j = 0; j < 4; j++) {
        *(float4*)&g_WhT[((size_t)bb * NF + nbase + tx * 4 + j) * NN
                         + rowb + ty * 4] =
            make_float4(acc[0][j], acc[1][j], acc[2][j], acc[3][j]);
    }
}

// ---------------- s1/s2 for the 8-head stage ----------------------------------
__global__ void sheads_kernel(const float* __restrict__ aheads, int l) {
    int w = threadIdx.x >> 5, lane = threadIdx.x & 31;
    int row = blockIdx.x * 8 + w;          // b*NN + n
    int b = row >> 11, n = row & (NN - 1);
    #pragma unroll
    for (int h = 0; h < NH; h++) {
        float v  = g_Wh[(size_t)row * NF + h * NO + lane];
        float a1 = aheads[((size_t)l * NH + h) * 2 * NO + lane];
        float a2 = aheads[((size_t)l * NH + h) * 2 * NO + NO + lane];
        float p1 = v * a1, p2 = v * a2;
        #pragma unroll
        for (int off = 16; off; off >>= 1) {
            p1 += __shfl_xor_sync(0xffffffffu, p1, off);
            p2 += __shfl_xor_sync(0xffffffffu, p2, off);
        }
        if (lane == 0) {
            g_s1[(b * NH + h) * NN + n] = p1;
            g_s2[(b * NH + h) * NN + n] = p2;
        }
    }
}

// ---------------- s1/s2 for the single-head out stage -------------------------
__global__ void sout_kernel(const float* __restrict__ aout, int l) {
    int w = threadIdx.x >> 5, lane = threadIdx.x & 31;
    int row = blockIdx.x * 8 + w;          // b*NN + n
    float p1 = 0.f, p2 = 0.f;
    #pragma unroll
    for (int k = 0; k < NF / 32; k++) {
        float v = g_Wh[(size_t)row * NF + k * 32 + lane];
        p1 += v * aout[(size_t)l * 2 * NF + k * 32 + lane];
        p2 += v * aout[(size_t)l * 2 * NF + NF + k * 32 + lane];
    }
    #pragma unroll
    for (int off = 16; off; off >>= 1) {
        p1 += __shfl_xor_sync(0xffffffffu, p1, off);
        p2 += __shfl_xor_sync(0xffffffffu, p2, off);
    }
    if (lane == 0) { g_s1[row] = p1; g_s2[row] = p2; }
}

// ---------------- fused masked-softmax attention + P@V + elu -----------------
// v6 = v5 compute core (RPW=4, FFMA2, ps layout) + cp.async double-buffered
// V^T tile loads from g_WhT (no in-kernel transpose), fused m2 prologue,
// per-tile uint4 mask hoist. grid (64, 8, NB), block 256.
#define JT  128
#define RPW 4
#define AW  8

__global__ void __launch_bounds__(256)
attn_kernel(float* __restrict__ oext, int osel,
            int spb, int symul, int elu2) {
    __shared__ __align__(16) float4 VT[2][1024];   // [buf][o*32 + (jc^o)]
    __shared__ __align__(16) float  s2t[2][JT];
    __shared__ __align__(16) float  ps[AW][RPW][32];
    __shared__ float red[AW];

    float* out = (osel == 0) ? g_hA : (osel == 1 ? g_h : oext);
    int b = blockIdx.z, y = blockIdx.y;
    int tid = threadIdx.x;
    int w = tid >> 5, lane = tid & 31;
    int vb = y * NO;
    int sidx = b * spb + y * symul;
    const float* s1p = g_s1 + (size_t)sidx * NN;
    const float* s2p = g_s2 + (size_t)sidx * NN;

    // fused m2: block-local max of s2 (any upper bound is valid for softmax)
    float mloc = -3.0e38f;
    for (int i = tid; i < NN; i += 256) mloc = fmaxf(mloc, s2p[i]);
    #pragma unroll
    for (int off = 16; off; off >>= 1)
        mloc = fmaxf(mloc, __shfl_xor_sync(0xffffffffu, mloc, off));
    if (lane == 0) red[w] = mloc;
    __syncthreads();
    float m2 = red[0];
    #pragma unroll
    for (int i = 1; i < AW; i++) m2 = fmaxf(m2, red[i]);

    int row0 = blockIdx.x * (AW * RPW) + w * RPW;

    float s1r[RPW], cir[RPW], lsum[RPW];
    ull acc2[RPW];
    const uint4* bmq[RPW];
    #pragma unroll
    for (int r = 0; r < RPW; r++) {
        s1r[r] = s1p[row0 + r];
        float t = s1r[r] + m2;
        cir[r] = fmaxf(t, 0.2f * t);
        acc2[r] = 0ull; lsum[r] = 0.f;
        bmq[r] = (const uint4*)(g_bm + ((size_t)(b * NN + row0 + r) << 6));
    }
    const float* WT = g_WhT + ((size_t)(b * NF + vb)) * NN;

    // ---- prologue: async-load tile 0 ----
    {
        #pragma unroll
        for (int k = 0; k < 4; k++) {
            int q = tid + 256 * k, o = q >> 5, jc = q & 31;
            cp16(&VT[0][(o << 5) | (jc ^ o)], WT + (size_t)o * NN + (jc << 2));
        }
        if (tid < 32) cp16(&s2t[0][tid * 4], s2p + tid * 4);
        CP_COMMIT();
    }

    for (int it = 0; it < NN / JT; it++) {
        int buf = it & 1;
        if (it + 1 < NN / JT) {       // prefetch next tile into alt buffer
            int jn = (it + 1) * JT;
            #pragma unroll
            for (int k = 0; k < 4; k++) {
                int q = tid + 256 * k, o = q >> 5, jc = q & 31;
                cp16(&VT[buf ^ 1][(o << 5) | (jc ^ o)],
                     WT + (size_t)o * NN + jn + (jc << 2));
            }
            if (tid < 32) cp16(&s2t[buf ^ 1][tid * 4], s2p + jn + tid * 4);
            CP_COMMIT();
            CP_WAIT1();
        } else {
            CP_WAIT0();
        }
        __syncthreads();

        uint4 mq[RPW];
        #pragma unroll
        for (int r = 0; r < RPW; r++) mq[r] = __ldg(&bmq[r][it]);

        #pragma unroll
        for (int c = 0; c < 4; c++) {
            float s2v = s2t[buf][c * 32 + lane];
            #pragma unroll
            for (int r = 0; r < RPW; r++) {
                unsigned mw = (c == 0) ? mq[r].x : (c == 1) ? mq[r].y
                            : (c == 2) ? mq[r].z : mq[r].w;
                float x = s1r[r] + s2v;
                float e = fmaxf(x, 0.2f * x);           // leakyrelu(0.2)
                float p = ((mw >> lane) & 1u) ? __expf(e - cir[r]) : 0.f;
                lsum[r] += p;
                ps[w][r][lane] = p;
            }
            __syncwarp();
            #pragma unroll
            for (int k4 = 0; k4 < 8; k4++) {
                const ull* vp = (const ull*)&VT[buf][(lane << 5) | ((c * 8 + k4) ^ lane)];
                ull vl = vp[0], vh = vp[1];
                #pragma unroll
                for (int r = 0; r < RPW; r++) {
                    const ull* pp = (const ull*)&ps[w][r][k4 * 4];
                    ffma2(acc2[r], pp[0], vl);
                    ffma2(acc2[r], pp[1], vh);
                }
            }
            __syncwarp();
        }
        __syncthreads();
    }

    #pragma unroll
    for (int r = 0; r < RPW; r++) {
        float l = lsum[r];
        #pragma unroll
        for (int off = 16; off; off >>= 1)
            l += __shfl_xor_sync(0xffffffffu, l, off);
        float2 ap = unpack2(acc2[r]);
        float v = (ap.x + ap.y) / l;
        v = (v > 0.f) ? v : (__expf(v) - 1.f);          // elu
        if (elu2) v = (v > 0.f) ? v : (__expf(v) - 1.f); // second elu (out stage)
        out[(size_t)(b * NN + row0 + r) * NF + vb + lane] = v;
    }
}

// ---------------- launch ------------------------------------------------------
extern "C" void kernel_launch(void* const* d_in, const int* in_sizes, int n_in,
                              void* d_out, int out_size) {
    const float* x       = (const float*)d_in[0];
    const int*   adj     = (const int*)  d_in[1];
    const float* W_heads = (const float*)d_in[2];
    const float* a_heads = (const float*)d_in[3];
    const float* W_out   = (const float*)d_in[4];
    const float* a_out   = (const float*)d_in[5];
    float* out = (float*)d_out;

    for (int l = 0; l < 3; l++) {
        // ---- stage A: 8-head GAT ----
        gemm_kernel<<<dim3(4, NB * NN / 64), 256>>>(
            l == 0 ? x : nullptr, W_heads + (size_t)l * NH * NF * NO,
            l == 0 ? 0 : 1, 0);
        sheads_kernel<<<NB * NN / 8, 256>>>(a_heads, l);
        if (l == 0) bm_kernel<<<NB * NN * 64 / 8, 256>>>(adj);
        attn_kernel<<<dim3(NN / (AW * RPW), 8, NB), 256>>>(nullptr, 0, NH, 1, 0);

        // ---- stage B: single-head out GAT (+extra elu) ----
        gemm_kernel<<<dim3(4, NB * NN / 64), 256>>>(
            nullptr, W_out + (size_t)l * NF * NF, 2, 1);
        sout_kernel<<<NB * NN / 8, 256>>>(a_out, l);
        attn_kernel<<<dim3(NN / (AW * RPW), 8, NB), 256>>>(
            l == 2 ? out : nullptr, l == 2 ? 2 : 1, 1, 0, 1);
    }
}